// round 13
// baseline (speedup 1.0000x reference)
#include <cuda_runtime.h>
#include <cuda_bf16.h>
#include <math.h>
#include <stdint.h>

#define NN 100000
#define EE 200000
#define GG 4096
#define DD 300
#define HH 600
#define LL 5
#define DECH 1200
#define MAXO 1783
// padded K dims (multiples of 32)
#define KPD 320
#define KPH 608
#define KPDEC 1216
#define DEC_ALL 7200              // 6*1200
#define DEC_ALLP 7296             // 6*1216

// ---------------- scratch (device globals) ----------------
__device__ float g_h [(size_t)NN*DD];
__device__ float g_z [(size_t)NN*DD];
__device__ float g_y [(size_t)NN*HH];
__device__ float g_stats[2*DEC_ALL];
__device__ float g_scale[DEC_ALL];
__device__ float g_shift[DEC_ALL];
__device__ unsigned g_hg[(size_t)GG*DD];
__device__ float g_d [(size_t)GG*HH];
__device__ float g_dz[(size_t)GG*DEC_ALL];
// bf16 hi/lo activation planes
__device__ __nv_bfloat16 g_zh[(size_t)NN*KPD],  g_zl[(size_t)NN*KPD];
__device__ __nv_bfloat16 g_yh[(size_t)NN*KPH],  g_yl[(size_t)NN*KPH];
__device__ __nv_bfloat16 g_sh[(size_t)GG*KPD],  g_sl[(size_t)GG*KPD];
__device__ __nv_bfloat16 g_muh[(size_t)GG*KPD], g_mul[(size_t)GG*KPD];
__device__ __nv_bfloat16 g_dzh[(size_t)GG*DEC_ALLP], g_dzl[(size_t)GG*DEC_ALLP];
// bf16 hi/lo transposed weights
__device__ __nv_bfloat16 g_w1th[(size_t)LL*HH*KPD],   g_w1tl[(size_t)LL*HH*KPD];
__device__ __nv_bfloat16 g_w2th[(size_t)LL*DD*KPH],   g_w2tl[(size_t)LL*DD*KPH];
__device__ __nv_bfloat16 g_dwth[(size_t)HH*KPD],      g_dwtl[(size_t)HH*KPD];
__device__ __nv_bfloat16 g_d1th[(size_t)6*DECH*KPD],  g_d1tl[(size_t)6*DECH*KPD];
__device__ __nv_bfloat16 g_d2th[(size_t)6*MAXO*KPDEC], g_d2tl[(size_t)6*MAXO*KPDEC];

// ================= helpers =================
__device__ __forceinline__ uint32_t smem_u32(const void* p) {
    uint32_t a;
    asm("{ .reg .u64 t; cvta.to.shared.u64 t, %1; cvt.u32.u64 %0, t; }" : "=r"(a) : "l"(p));
    return a;
}
__device__ __forceinline__ void split_bf(float v, __nv_bfloat16& h, __nv_bfloat16& l) {
    h = __float2bfloat16(v);
    l = __float2bfloat16(v - __bfloat162float(h));
}
__device__ __forceinline__ uint32_t pk2(__nv_bfloat16 a, __nv_bfloat16 b) {
    return (uint32_t)__bfloat16_as_ushort(a) | ((uint32_t)__bfloat16_as_ushort(b) << 16);
}
__device__ __forceinline__ void split4(float4 v, uint2& hi, uint2& lo) {
    __nv_bfloat16 hx, hy, hz, hw, lx, ly, lz, lw;
    split_bf(v.x, hx, lx); split_bf(v.y, hy, ly);
    split_bf(v.z, hz, lz); split_bf(v.w, hw, lw);
    hi = make_uint2(pk2(hx, hy), pk2(hz, hw));
    lo = make_uint2(pk2(lx, ly), pk2(lz, lw));
}
#define LDSM_X4(r, a) \
    asm volatile("ldmatrix.sync.aligned.m8n8.x4.shared.b16 {%0,%1,%2,%3}, [%4];" \
        : "=r"((r)[0]), "=r"((r)[1]), "=r"((r)[2]), "=r"((r)[3]) : "r"(a))
__device__ __forceinline__ void mma_bf16(float* c, const uint32_t* a, const uint32_t* b) {
    asm volatile("mma.sync.aligned.m16n8k16.row.col.f32.bf16.bf16.f32 "
        "{%0,%1,%2,%3}, {%4,%5,%6,%7}, {%8,%9}, {%0,%1,%2,%3};"
        : "+f"(c[0]), "+f"(c[1]), "+f"(c[2]), "+f"(c[3])
        : "r"(a[0]), "r"(a[1]), "r"(a[2]), "r"(a[3]), "r"(b[0]), "r"(b[1]));
}
__device__ __forceinline__ void cpa16(uint32_t dst, const void* src, int bytes) {
    asm volatile("cp.async.cg.shared.global [%0], [%1], 16, %2;"
        :: "r"(dst), "l"(src), "r"(bytes) : "memory");
}
#define CPA_COMMIT() asm volatile("cp.async.commit_group;" ::: "memory")
#define CPA_WAIT0()  asm volatile("cp.async.wait_group 0;" ::: "memory")

// ============ HMMA GEMM: TM64 x TN128 x TK32, 3 CTAs/SM ============
#define TM 64
#define TN 128
#define TK 32
#define PITCH 40                 // bf16 elems per smem row (80B)
#define OFF_AL 5120              // A: 64 rows x 80B per plane
#define OFF_BH 10240             // B: 128 rows x 80B per plane
#define OFF_BL 20480
#define STAGE_B 30720
#define GEMM_SMEM (2 * STAGE_B)

#define GEMM_LOADER(T, BUF, AhP, AlP, BhP, BlP, LDA, LDB, R0, C0, MM, NCC) do { \
    int kt = (T) * TK; \
    uint32_t sst = sbase + (uint32_t)(BUF) * STAGE_B; \
    _Pragma("unroll") \
    for (int q = 0; q < 6; q++) { \
        int idx = tid + q * 256; \
        int row = idx >> 2, k8 = idx & 3; \
        const __nv_bfloat16* base; int gr, ld, lim; uint32_t off; \
        if (row < 128) { \
            base = (row < 64) ? (AhP) : (AlP); \
            gr = (R0) + (row & 63); ld = (LDA); lim = (MM); \
            off = ((row < 64) ? 0u : (uint32_t)OFF_AL) + (uint32_t)(row & 63) * 80; \
        } else { \
            int br = row - 128; \
            base = (br < 128) ? (BhP) : (BlP); \
            gr = (C0) + (br & 127); ld = (LDB); lim = (NCC); \
            off = (uint32_t)OFF_BH + ((br < 128) ? 0u : 10240u) + (uint32_t)(br & 127) * 80; \
        } \
        int ok = (gr < lim) ? 16 : 0; \
        int grc = (gr < lim) ? gr : 0; \
        cpa16(sst + off + k8 * 16, base + (size_t)grc * ld + kt + k8 * 8, ok); \
    } } while (0)

#define GEMM_MAINLOOP(AhP, AlP, BhP, BlP, LDA, LDB, R0, C0, MM, NCC, KPV) do { \
    int nt = (KPV) / TK; \
    GEMM_LOADER(0, 0, AhP, AlP, BhP, BlP, LDA, LDB, R0, C0, MM, NCC); CPA_COMMIT(); \
    int a_r = lane & 15; \
    int a_c = (lane >> 4) << 3; \
    int b_r = (lane & 7) + ((lane & 16) >> 1); \
    int b_c = ((lane >> 3) & 1) << 3; \
    for (int t = 0; t < nt; t++) { \
        CPA_WAIT0(); \
        __syncthreads(); \
        int buf = t & 1; \
        if (t + 1 < nt) { GEMM_LOADER(t + 1, buf ^ 1, AhP, AlP, BhP, BlP, LDA, LDB, R0, C0, MM, NCC); } \
        CPA_COMMIT(); \
        uint32_t sA = sbase + (uint32_t)buf * STAGE_B; \
        uint32_t sB = sA + OFF_BH; \
        _Pragma("unroll") \
        for (int kk = 0; kk < TK; kk += 16) { \
            uint32_t ah[2][4], al[2][4], bh[2][4], bl[2][4]; \
            _Pragma("unroll") \
            for (int i = 0; i < 2; i++) { \
                uint32_t ad = sA + (uint32_t)((wm * 32 + i * 16 + a_r) * PITCH + kk + a_c) * 2; \
                LDSM_X4(ah[i], ad); \
                LDSM_X4(al[i], ad + OFF_AL); \
            } \
            _Pragma("unroll") \
            for (int jj = 0; jj < 2; jj++) { \
                uint32_t bd = sB + (uint32_t)((wn * 32 + jj * 16 + b_r) * PITCH + kk + b_c) * 2; \
                LDSM_X4(bh[jj], bd); \
                LDSM_X4(bl[jj], bd + 10240); \
            } \
            _Pragma("unroll") \
            for (int i = 0; i < 2; i++) \
                _Pragma("unroll") \
                for (int jj = 0; jj < 2; jj++) \
                    _Pragma("unroll") \
                    for (int jx = 0; jx < 2; jx++) { \
                        int j = jj * 2 + jx; \
                        mma_bf16(acc[i][j], ah[i], &bh[jj][jx * 2]); \
                        mma_bf16(acc[i][j], ah[i], &bl[jj][jx * 2]); \
                        mma_bf16(acc[i][j], al[i], &bh[jj][jx * 2]); \
                    } \
        } \
    } } while (0)

__global__ void __launch_bounds__(256, 3) k_tgemm(
    const __nv_bfloat16* __restrict__ Ah, const __nv_bfloat16* __restrict__ Al, int lda,
    const __nv_bfloat16* __restrict__ Bh, const __nv_bfloat16* __restrict__ Bl, int ldb,
    const float* __restrict__ bias,
    float* __restrict__ C, int ldc,
    int M, int Nc, int Kp,
    float* __restrict__ stats, int do_stats)
{
    extern __shared__ char smem[];
    uint32_t sbase = smem_u32(smem);
    int tid = threadIdx.x, wid = tid >> 5, lane = tid & 31;
    int row0 = blockIdx.y * TM;
    int col0 = blockIdx.x * TN;
    int wm = wid & 1, wn = wid >> 1;   // warp tile: rows wm*32..+31, cols wn*32..+31

    float acc[2][4][4];
#pragma unroll
    for (int i = 0; i < 2; i++)
#pragma unroll
        for (int j = 0; j < 4; j++)
#pragma unroll
            for (int q = 0; q < 4; q++) acc[i][j][q] = 0.f;

    GEMM_MAINLOOP(Ah, Al, Bh, Bl, lda, ldb, row0, col0, M, Nc, Kp);

    int g = lane >> 2, t4 = lane & 3;
#pragma unroll
    for (int i = 0; i < 2; i++) {
        int r0c = row0 + wm * 32 + i * 16 + g;
        bool rv0 = (r0c < M), rv1 = (r0c + 8 < M);
#pragma unroll
        for (int j = 0; j < 4; j++) {
            int c0c = col0 + wn * 32 + j * 8 + t4 * 2;
            bool cv0 = (c0c < Nc), cv1 = (c0c + 1 < Nc);
            float b0 = cv0 ? bias[c0c] : 0.f;
            float b1 = cv1 ? bias[c0c + 1] : 0.f;
            float v0 = acc[i][j][0] + b0, v1 = acc[i][j][1] + b1;
            float v2 = acc[i][j][2] + b0, v3 = acc[i][j][3] + b1;
            if (rv0 && cv0) C[(size_t)r0c * ldc + c0c] = v0;
            if (rv0 && cv1) C[(size_t)r0c * ldc + c0c + 1] = v1;
            if (rv1 && cv0) C[(size_t)(r0c + 8) * ldc + c0c] = v2;
            if (rv1 && cv1) C[(size_t)(r0c + 8) * ldc + c0c + 1] = v3;
            acc[i][j][0] = (rv0 && cv0) ? v0 : 0.f;
            acc[i][j][1] = (rv0 && cv1) ? v1 : 0.f;
            acc[i][j][2] = (rv1 && cv0) ? v2 : 0.f;
            acc[i][j][3] = (rv1 && cv1) ? v3 : 0.f;
        }
    }
    if (do_stats) {
#pragma unroll
        for (int j = 0; j < 4; j++) {
            float se = 0.f, so = 0.f, qe = 0.f, qo = 0.f;
#pragma unroll
            for (int i = 0; i < 2; i++) {
                float v0 = acc[i][j][0], v1 = acc[i][j][1];
                float v2 = acc[i][j][2], v3 = acc[i][j][3];
                se += v0 + v2; so += v1 + v3;
                qe += v0 * v0 + v2 * v2; qo += v1 * v1 + v3 * v3;
            }
#pragma unroll
            for (int off = 4; off < 32; off <<= 1) {
                se += __shfl_xor_sync(0xffffffffu, se, off);
                so += __shfl_xor_sync(0xffffffffu, so, off);
                qe += __shfl_xor_sync(0xffffffffu, qe, off);
                qo += __shfl_xor_sync(0xffffffffu, qo, off);
            }
            if (lane < 4) {
                int ce = col0 + wn * 32 + j * 8 + lane * 2;
                if (ce < Nc)     { atomicAdd(&stats[ce], se);     atomicAdd(&stats[Nc + ce], qe); }
                if (ce + 1 < Nc) { atomicAdd(&stats[ce + 1], so); atomicAdd(&stats[Nc + ce + 1], qo); }
            }
        }
    }
}

// ======== batched decoder head-2 GEMM: blockIdx.z = head ========
__global__ void __launch_bounds__(256, 3) k_tgemm_dec2(
    const __nv_bfloat16* __restrict__ AhAll, const __nv_bfloat16* __restrict__ AlAll,
    const __nv_bfloat16* __restrict__ BhAll, const __nv_bfloat16* __restrict__ BlAll,
    const float* __restrict__ biasAll,
    float* __restrict__ outBase)
{
    const int DIMS[6] = {1024, 1111, 862, 1783, 966, 978};
    const int LDCS[6] = {1024, 1973, 1973, 2749, 2749, 978};
    const long BASE[6] = {
        2L * GG * DD,
        2L * GG * DD + (long)GG * 1024,
        2L * GG * DD + (long)GG * 1024 + 1111,
        2L * GG * DD + (long)GG * 1024 + (long)GG * 1973,
        2L * GG * DD + (long)GG * 1024 + (long)GG * 1973 + 1783,
        2L * GG * DD + (long)GG * 1024 + (long)GG * 1973 + (long)GG * 2749
    };
    int head = blockIdx.z;
    int Nc = DIMS[head];
    int ldc = LDCS[head];
    int col0 = blockIdx.x * TN;
    if (col0 >= Nc) return;
    int row0 = blockIdx.y * TM;
    const __nv_bfloat16* Ah = AhAll + (size_t)head * KPDEC;
    const __nv_bfloat16* Al = AlAll + (size_t)head * KPDEC;
    const __nv_bfloat16* Bh = BhAll + (size_t)head * MAXO * KPDEC;
    const __nv_bfloat16* Bl = BlAll + (size_t)head * MAXO * KPDEC;
    const float* bias = biasAll + (size_t)head * MAXO;
    float* C = outBase + BASE[head];
    const int lda = DEC_ALLP, ldb = KPDEC;

    extern __shared__ char smem[];
    uint32_t sbase = smem_u32(smem);
    int tid = threadIdx.x, wid = tid >> 5, lane = tid & 31;
    int wm = wid & 1, wn = wid >> 1;

    float acc[2][4][4];
#pragma unroll
    for (int i = 0; i < 2; i++)
#pragma unroll
        for (int j = 0; j < 4; j++)
#pragma unroll
            for (int q = 0; q < 4; q++) acc[i][j][q] = 0.f;

    GEMM_MAINLOOP(Ah, Al, Bh, Bl, lda, ldb, row0, col0, GG, Nc, KPDEC);

    int g = lane >> 2, t4 = lane & 3;
#pragma unroll
    for (int i = 0; i < 2; i++) {
        int r0c = row0 + wm * 32 + i * 16 + g;
#pragma unroll
        for (int j = 0; j < 4; j++) {
            int c0c = col0 + wn * 32 + j * 8 + t4 * 2;
            bool cv0 = (c0c < Nc), cv1 = (c0c + 1 < Nc);
            float b0 = cv0 ? bias[c0c] : 0.f;
            float b1 = cv1 ? bias[c0c + 1] : 0.f;
            if (cv0) C[(size_t)r0c * ldc + c0c] = acc[i][j][0] + b0;
            if (cv1) C[(size_t)r0c * ldc + c0c + 1] = acc[i][j][1] + b1;
            if (cv0) C[(size_t)(r0c + 8) * ldc + c0c] = acc[i][j][2] + b0;
            if (cv1) C[(size_t)(r0c + 8) * ldc + c0c + 1] = acc[i][j][3] + b1;
        }
    }
}

// ============ weight transpose + hi/lo convert (batched) ============
__global__ void k_wcvt(const float* __restrict__ in,
                       __nv_bfloat16* __restrict__ hi, __nv_bfloat16* __restrict__ lo,
                       int K, int N, int Kp) {
    __shared__ float t[32][33];
    int b = blockIdx.z;
    const float* I = in + (size_t)b * K * N;
    __nv_bfloat16* H = hi + (size_t)b * N * Kp;
    __nv_bfloat16* L = lo + (size_t)b * N * Kp;
    int r0 = blockIdx.y * 32, c0 = blockIdx.x * 32;
    int c = c0 + threadIdx.x;
#pragma unroll
    for (int i = 0; i < 32; i += 8) {
        int r = r0 + threadIdx.y + i;
        t[threadIdx.y + i][threadIdx.x] = (r < K && c < N) ? I[(size_t)r * N + c] : 0.f;
    }
    __syncthreads();
    int k = r0 + threadIdx.x;
#pragma unroll
    for (int i = 0; i < 32; i += 8) {
        int n = c0 + threadIdx.y + i;
        if (n < N && k < Kp) {
            float v = t[threadIdx.x][threadIdx.y + i];
            __nv_bfloat16 h, l; split_bf(v, h, l);
            H[(size_t)n * Kp + k] = h;
            L[(size_t)n * Kp + k] = l;
        }
    }
}

// vectorized fp32 -> padded bf16 hi/lo; also zeroes stats[0..zcount)
__global__ void k_cvtpad4(const float* __restrict__ in,
                          uint2* __restrict__ hi, uint2* __restrict__ lo,
                          long total4, int C, int Cp,
                          float* __restrict__ stats, int zcount) {
    long i = (long)blockIdx.x * blockDim.x + threadIdx.x;
    if (i >= total4) return;
    if (stats && i < zcount) stats[i] = 0.f;
    int w4 = Cp >> 2;
    int n = (int)(i / w4);
    int c = ((int)(i - (long)n * w4)) << 2;
    float4 v = make_float4(0.f, 0.f, 0.f, 0.f);
    if (c < C) v = *(const float4*)(in + (size_t)n * C + c);
    uint2 h, l; split4(v, h, l);
    hi[i] = h; lo[i] = l;
}

// BN apply + act + hi/lo convert, head-batched; also zeroes stats[0..zcount)
__global__ void k_bnact_cvt4(const float* __restrict__ X,
                             const float* __restrict__ scale, const float* __restrict__ shift,
                             uint2* __restrict__ hi, uint2* __restrict__ lo,
                             long total4, int C, int Cp, int nheads, int gelu,
                             float* __restrict__ stats, int zcount) {
    long i = (long)blockIdx.x * blockDim.x + threadIdx.x;
    if (i >= total4) return;
    if (stats && i < zcount) stats[i] = 0.f;
    int w4 = (nheads * Cp) >> 2;
    int n = (int)(i / w4);
    int col = ((int)(i - (long)n * w4)) << 2;
    int head = col / Cp;
    int c = col - head * Cp;
    float4 r4 = make_float4(0.f, 0.f, 0.f, 0.f);
    if (c < C) {
        int sidx = head * C + c;
        const float4 x = *(const float4*)(X + (size_t)n * (nheads * C) + sidx);
        const float4 sc = *(const float4*)(scale + sidx);
        const float4 sh = *(const float4*)(shift + sidx);
        float v0 = x.x * sc.x + sh.x, v1 = x.y * sc.y + sh.y;
        float v2 = x.z * sc.z + sh.z, v3 = x.w * sc.w + sh.w;
        if (gelu) {
            const float k = 0.70710678118654752f;
            r4 = make_float4(0.5f * v0 * (1.f + erff(v0 * k)), 0.5f * v1 * (1.f + erff(v1 * k)),
                             0.5f * v2 * (1.f + erff(v2 * k)), 0.5f * v3 * (1.f + erff(v3 * k)));
        } else {
            r4 = make_float4(fmaxf(v0, 0.f), fmaxf(v1, 0.f), fmaxf(v2, 0.f), fmaxf(v3, 0.f));
        }
    }
    uint2 h, l; split4(r4, h, l);
    hi[i] = h; lo[i] = l;
}

// ================= elementwise =================
__global__ void k_zero_u(unsigned* p, int n) {
    int i = blockIdx.x * blockDim.x + threadIdx.x;
    if (i < n) p[i] = 0u;
}
// h = atom_emb[x_idx]; z = (1+eps0)*h
__global__ void k_init_h4(const float4* __restrict__ atom_emb, const int* __restrict__ x_idx,
                          const float* __restrict__ eps0,
                          float4* __restrict__ h, float4* __restrict__ z) {
    long i = (long)blockIdx.x * blockDim.x + threadIdx.x;
    const int C4 = DD / 4;
    long total = (long)NN * C4;
    if (i >= total) return;
    int n = (int)(i / C4);
    int d = (int)(i - (long)n * C4);
    float4 v = atom_emb[(size_t)x_idx[n] * C4 + d];
    h[i] = v;
    float e = 1.f + *eps0;
    z[i] = make_float4(e * v.x, e * v.y, e * v.z, e * v.w);
}
// edge: msg = relu(h[src]+e); vector RED into z[dst]
__global__ void k_edge4(const float4* __restrict__ h, const float4* __restrict__ ee,
                        const int* __restrict__ attr, const int* __restrict__ ei,
                        float* __restrict__ z) {
    long i = (long)blockIdx.x * blockDim.x + threadIdx.x;
    const int C4 = DD / 4;
    long total = (long)EE * C4;
    if (i >= total) return;
    int e = (int)(i / C4);
    int q = (int)(i - (long)e * C4);
    int src = ei[e];
    int dst = ei[EE + e];
    float4 a = h[(size_t)src * C4 + q];
    float4 b = ee[(size_t)attr[e] * C4 + q];
    float m0 = fmaxf(a.x + b.x, 0.f);
    float m1 = fmaxf(a.y + b.y, 0.f);
    float m2 = fmaxf(a.z + b.z, 0.f);
    float m3 = fmaxf(a.w + b.w, 0.f);
    float* zp = z + (size_t)dst * DD + q * 4;
    asm volatile("red.global.add.v4.f32 [%0], {%1,%2,%3,%4};"
        :: "l"(zp), "f"(m0), "f"(m1), "f"(m2), "f"(m3) : "memory");
}
__global__ void k_bn_final(const float* __restrict__ sums, float invM, int C,
                           const float* __restrict__ gamma, const float* __restrict__ beta,
                           float* __restrict__ scale, float* __restrict__ shift) {
    int c = blockIdx.x * blockDim.x + threadIdx.x;
    if (c >= C) return;
    float mean = sums[c] * invM;
    float var  = sums[C + c] * invM - mean * mean;
    float istd = rsqrtf(var + 1e-5f);
    float sc = istd * gamma[c];
    scale[c] = sc;
    shift[c] = beta[c] - mean * sc;
}
// mode 1: h += relu(bn(X)); mode 2: h += bn(X). If znext: znext = (1+eps)*h_new.
__global__ void k_bn_apply4(float4* __restrict__ X, float4* __restrict__ res,
                            const float4* __restrict__ scale, const float4* __restrict__ shift,
                            long total4, int C4, int mode,
                            const float* __restrict__ epsn, float4* __restrict__ znext) {
    long i = (long)blockIdx.x * blockDim.x + threadIdx.x;
    if (i >= total4) return;
    int c = (int)(i % C4);
    float4 x = X[i], sc = scale[c], sh = shift[c];
    float v0 = x.x * sc.x + sh.x, v1 = x.y * sc.y + sh.y;
    float v2 = x.z * sc.z + sh.z, v3 = x.w * sc.w + sh.w;
    float4 r = res[i];
    float4 o;
    if (mode == 1) {
        o = make_float4(r.x + fmaxf(v0, 0.f), r.y + fmaxf(v1, 0.f),
                        r.z + fmaxf(v2, 0.f), r.w + fmaxf(v3, 0.f));
    } else {
        o = make_float4(r.x + v0, r.y + v1, r.z + v2, r.w + v3);
    }
    res[i] = o;
    if (znext) {
        float e = 1.f + *epsn;
        znext[i] = make_float4(e * o.x, e * o.y, e * o.z, e * o.w);
    }
}
__device__ __forceinline__ unsigned enc_f(float x) {
    unsigned u = __float_as_uint(x);
    return (u & 0x80000000u) ? ~u : (u | 0x80000000u);
}
__global__ void k_segmax(const float* __restrict__ h, const int* __restrict__ batch,
                         unsigned* __restrict__ hg) {
    long i = (long)blockIdx.x * blockDim.x + threadIdx.x;
    long total = (long)NN * DD;
    if (i >= total) return;
    int n = (int)(i / DD);
    int d = (int)(i - (long)n * DD);
    atomicMax(&hg[(size_t)batch[n] * DD + d], enc_f(h[i]));
}
__global__ void k_silu_cvt4(const unsigned* __restrict__ hg,
                            uint2* __restrict__ hi, uint2* __restrict__ lo,
                            long total4, int C, int Cp) {
    long i = (long)blockIdx.x * blockDim.x + threadIdx.x;
    if (i >= total4) return;
    int w4 = Cp >> 2;
    int n = (int)(i / w4);
    int c = ((int)(i - (long)n * w4)) << 2;
    float4 r4 = make_float4(0.f, 0.f, 0.f, 0.f);
    if (c < C) {
        uint4 u4 = *(const uint4*)(hg + (size_t)n * C + c);
        float* rp = &r4.x;
        unsigned uu[4] = {u4.x, u4.y, u4.z, u4.w};
#pragma unroll
        for (int q = 0; q < 4; q++) {
            unsigned u = uu[q];
            u = (u & 0x80000000u) ? (u & 0x7fffffffu) : ~u;
            float x = __uint_as_float(u);
            rp[q] = x / (1.f + expf(-x));
        }
    }
    uint2 h, l; split4(r4, h, l);
    hi[i] = h; lo[i] = l;
}
__global__ void k_split(const float* __restrict__ d, float* __restrict__ out, long offS) {
    long i = (long)blockIdx.x * blockDim.x + threadIdx.x;
    long total = (long)GG * HH;
    if (i >= total) return;
    int g = (int)(i / HH);
    int c = (int)(i - (long)g * HH);
    float v = d[i];
    if (c < DD) {
        out[(size_t)g * DD + c] = v;
    } else {
        float sp = fmaxf(v, 0.f) + log1pf(expf(-fabsf(v))) + 1e-7f;
        out[offS + (size_t)g * DD + (c - DD)] = sp;
    }
}

// ================= host side =================
static void tgemm(const __nv_bfloat16* Ah, const __nv_bfloat16* Al, int lda,
                  const __nv_bfloat16* Bh, const __nv_bfloat16* Bl, int ldb,
                  const float* bias, float* C, int ldc,
                  int M, int Nc, int Kp, float* stats, int do_stats) {
    dim3 gr((Nc + TN - 1) / TN, (M + TM - 1) / TM);
    k_tgemm<<<gr, 256, GEMM_SMEM>>>(Ah, Al, lda, Bh, Bl, ldb, bias, C, ldc, M, Nc, Kp, stats, do_stats);
}
static void wcvt(const float* in, __nv_bfloat16* hi, __nv_bfloat16* lo,
                 int K, int N, int Kp, int B) {
    dim3 bl(32, 8), gr((N + 31) / 32, (Kp + 31) / 32, B);
    k_wcvt<<<gr, bl>>>(in, hi, lo, K, N, Kp);
}

extern "C" void kernel_launch(void* const* d_in, const int* in_sizes, int n_in,
                              void* d_out, int out_size) {
    const float* atom_emb   = (const float*)d_in[0];
    const float* edge_emb   = (const float*)d_in[1];
    const float* eps        = (const float*)d_in[2];
    const float* conv_w1    = (const float*)d_in[3];
    const float* conv_b1    = (const float*)d_in[4];
    const float* conv_bn1_g = (const float*)d_in[5];
    const float* conv_bn1_b = (const float*)d_in[6];
    const float* conv_w2    = (const float*)d_in[7];
    const float* conv_b2    = (const float*)d_in[8];
    const float* bn_g       = (const float*)d_in[9];
    const float* bn_b       = (const float*)d_in[10];
    const float* dist_w     = (const float*)d_in[11];
    const float* dist_b     = (const float*)d_in[12];
    const float* dec_w1     = (const float*)d_in[13];
    const float* dec_b1     = (const float*)d_in[14];
    const float* dec_bn_g   = (const float*)d_in[15];
    const float* dec_bn_b   = (const float*)d_in[16];
    const float* dec_w2     = (const float*)d_in[17];
    const float* dec_b2     = (const float*)d_in[18];
    const int*   x_idx      = (const int*)d_in[19];
    const int*   edge_attr  = (const int*)d_in[20];
    const int*   edge_index = (const int*)d_in[21];
    const int*   batch      = (const int*)d_in[22];
    float* out = (float*)d_out;

    cudaFuncSetAttribute(k_tgemm, cudaFuncAttributeMaxDynamicSharedMemorySize, GEMM_SMEM);
    cudaFuncSetAttribute(k_tgemm_dec2, cudaFuncAttributeMaxDynamicSharedMemorySize, GEMM_SMEM);

    float *h, *z, *y, *stats, *scale, *shift, *dbuf, *dz;
    unsigned* hg;
    __nv_bfloat16 *zh, *zl, *yh, *yl, *sh, *sl, *muh, *mul, *dzh, *dzl;
    __nv_bfloat16 *w1th, *w1tl, *w2th, *w2tl, *dwth, *dwtl, *d1th, *d1tl, *d2th, *d2tl;
    cudaGetSymbolAddress((void**)&h,     g_h);
    cudaGetSymbolAddress((void**)&z,     g_z);
    cudaGetSymbolAddress((void**)&y,     g_y);
    cudaGetSymbolAddress((void**)&stats, g_stats);
    cudaGetSymbolAddress((void**)&scale, g_scale);
    cudaGetSymbolAddress((void**)&shift, g_shift);
    cudaGetSymbolAddress((void**)&hg,    g_hg);
    cudaGetSymbolAddress((void**)&dbuf,  g_d);
    cudaGetSymbolAddress((void**)&dz,    g_dz);
    cudaGetSymbolAddress((void**)&zh,    g_zh);   cudaGetSymbolAddress((void**)&zl,  g_zl);
    cudaGetSymbolAddress((void**)&yh,    g_yh);   cudaGetSymbolAddress((void**)&yl,  g_yl);
    cudaGetSymbolAddress((void**)&sh,    g_sh);   cudaGetSymbolAddress((void**)&sl,  g_sl);
    cudaGetSymbolAddress((void**)&muh,   g_muh);  cudaGetSymbolAddress((void**)&mul, g_mul);
    cudaGetSymbolAddress((void**)&dzh,   g_dzh);  cudaGetSymbolAddress((void**)&dzl, g_dzl);
    cudaGetSymbolAddress((void**)&w1th,  g_w1th); cudaGetSymbolAddress((void**)&w1tl, g_w1tl);
    cudaGetSymbolAddress((void**)&w2th,  g_w2th); cudaGetSymbolAddress((void**)&w2tl, g_w2tl);
    cudaGetSymbolAddress((void**)&dwth,  g_dwth); cudaGetSymbolAddress((void**)&dwtl, g_dwtl);
    cudaGetSymbolAddress((void**)&d1th,  g_d1th); cudaGetSymbolAddress((void**)&d1tl, g_d1tl);
    cudaGetSymbolAddress((void**)&d2th,  g_d2th); cudaGetSymbolAddress((void**)&d2tl, g_d2tl);

    // transpose + convert weights once per call
    wcvt(conv_w1, w1th, w1tl, DD, HH, KPD, LL);
    wcvt(conv_w2, w2th, w2tl, HH, DD, KPH, LL);
    wcvt(dist_w,  dwth, dwtl, DD, HH, KPD, 1);
    wcvt(dec_w1,  d1th, d1tl, DD, DECH, KPD, 6);
    wcvt(dec_w2,  d2th, d2tl, DECH, MAXO, KPDEC, 6);

    const long ND  = (long)NN * DD;
    const long ND4 = ND / 4;
    const long ED4 = (long)EE * DD / 4;
    const long NZP4 = (long)NN * KPD / 4;
    const long NYP4 = (long)NN * KPH / 4;

    k_init_h4<<<(int)((ND4 + 255) / 256), 256>>>((const float4*)atom_emb, x_idx, eps,
                                                 (float4*)h, (float4*)z);

    for (int l = 0; l < LL; l++) {
        k_edge4<<<(int)((ED4 + 255) / 256), 256>>>((const float4*)h,
                 (const float4*)(edge_emb + (size_t)l * 5 * DD), edge_attr, edge_index, z);
        k_cvtpad4<<<(int)((NZP4 + 255) / 256), 256>>>(z, (uint2*)zh, (uint2*)zl, NZP4, DD, KPD,
                                                      stats, 2 * HH);
        tgemm(zh, zl, KPD, w1th + (size_t)l * HH * KPD, w1tl + (size_t)l * HH * KPD, KPD,
              conv_b1 + (size_t)l * HH, y, HH, NN, HH, KPD, stats, 1);
        k_bn_final<<<(HH + 255) / 256, 256>>>(stats, 1.f / (float)NN, HH,
              conv_bn1_g + (size_t)l * HH, conv_bn1_b + (size_t)l * HH, scale, shift);
        k_bnact_cvt4<<<(int)((NYP4 + 255) / 256), 256>>>(y, scale, shift,
              (uint2*)yh, (uint2*)yl, NYP4, HH, KPH, 1, 0, stats, 2 * DD);
        tgemm(yh, yl, KPH, w2th + (size_t)l * DD * KPH, w2tl + (size_t)l * DD * KPH, KPH,
              conv_b2 + (size_t)l * DD, z, DD, NN, DD, KPH, stats, 1);
        k_bn_final<<<(DD + 255) / 256, 256>>>(stats, 1.f / (float)NN, DD,
              bn_g + (size_t)l * DD, bn_b + (size_t)l * DD, scale, shift);
        bool more = (l < LL - 1);
        k_bn_apply4<<<(int)((ND4 + 255) / 256), 256>>>((float4*)z, (float4*)h,
              (const float4*)scale, (const float4*)shift, ND4, DD / 4, more ? 1 : 2,
              more ? (eps + l + 1) : nullptr, more ? (float4*)z : nullptr);
    }

    // pooling -> silu -> bf16
    int GD = GG * DD;
    const long GSP4 = (long)GG * KPD / 4;
    k_zero_u<<<(GD + 255) / 256, 256>>>(hg, GD);
    k_segmax<<<(int)((ND + 255) / 256), 256>>>(h, batch, hg);
    k_silu_cvt4<<<(int)((GSP4 + 255) / 256), 256>>>(hg, (uint2*)sh, (uint2*)sl, GSP4, DD, KPD);

    // d = silu(h_graph) @ dist_w + dist_b
    tgemm(sh, sl, KPD, dwth, dwtl, KPD, dist_b, dbuf, HH, GG, HH, KPD, stats, 0);

    const long OFF_SG = (long)GG * DD;
    k_split<<<(int)(((long)GG * HH + 255) / 256), 256>>>(dbuf, out, OFF_SG);
    k_cvtpad4<<<(int)((GSP4 + 255) / 256), 256>>>(out, (uint2*)muh, (uint2*)mul, GSP4, DD, KPD,
                                                  stats, 2 * DEC_ALL);

    // ===== batched decoder heads =====
    tgemm(muh, mul, KPD, d1th, d1tl, KPD, dec_b1, dz, DEC_ALL, GG, DEC_ALL, KPD, stats, 1);
    k_bn_final<<<(DEC_ALL + 255) / 256, 256>>>(stats, 1.f / (float)GG, DEC_ALL,
          dec_bn_g, dec_bn_b, scale, shift);
    const long GDP4 = (long)GG * DEC_ALLP / 4;
    k_bnact_cvt4<<<(int)((GDP4 + 255) / 256), 256>>>(dz, scale, shift,
          (uint2*)dzh, (uint2*)dzl, GDP4, DECH, KPDEC, 6, 1, nullptr, 0);
    {
        dim3 gr((MAXO + TN - 1) / TN, (GG + TM - 1) / TM, 6);
        k_tgemm_dec2<<<gr, 256, GEMM_SMEM>>>(dzh, dzl, d2th, d2tl, dec_b2, out);
    }
}

// round 14
// speedup vs baseline: 1.5385x; 1.5385x over previous
#include <cuda_runtime.h>
#include <cuda_bf16.h>
#include <math.h>
#include <stdint.h>

#define NN 100000
#define EE 200000
#define GG 4096
#define DD 300
#define HH 600
#define LL 5
#define DECH 1200
#define MAXO 1783
// padded K dims (multiples of 32)
#define KPD 320
#define KPH 608
#define KPDEC 1216
#define DEC_ALL 7200              // 6*1200
#define DEC_ALLP 7296             // 6*1216

// ---------------- scratch (device globals) ----------------
__device__ float g_h [(size_t)NN*DD];
__device__ float g_z [(size_t)NN*DD];
__device__ float g_y [(size_t)NN*HH];
__device__ float g_stats[2*DEC_ALL];
__device__ float g_scale[DEC_ALL];
__device__ float g_shift[DEC_ALL];
__device__ unsigned g_hg[(size_t)GG*DD];
__device__ float g_d [(size_t)GG*HH];
__device__ float g_dz[(size_t)GG*DEC_ALL];
// bf16 hi/lo activation planes
__device__ __nv_bfloat16 g_zh[(size_t)NN*KPD],  g_zl[(size_t)NN*KPD];
__device__ __nv_bfloat16 g_yh[(size_t)NN*KPH],  g_yl[(size_t)NN*KPH];
__device__ __nv_bfloat16 g_sh[(size_t)GG*KPD],  g_sl[(size_t)GG*KPD];
__device__ __nv_bfloat16 g_muh[(size_t)GG*KPD], g_mul[(size_t)GG*KPD];
__device__ __nv_bfloat16 g_dzh[(size_t)GG*DEC_ALLP], g_dzl[(size_t)GG*DEC_ALLP];
// bf16 hi/lo transposed weights
__device__ __nv_bfloat16 g_w1th[(size_t)LL*HH*KPD],   g_w1tl[(size_t)LL*HH*KPD];
__device__ __nv_bfloat16 g_w2th[(size_t)LL*DD*KPH],   g_w2tl[(size_t)LL*DD*KPH];
__device__ __nv_bfloat16 g_dwth[(size_t)HH*KPD],      g_dwtl[(size_t)HH*KPD];
__device__ __nv_bfloat16 g_d1th[(size_t)6*DECH*KPD],  g_d1tl[(size_t)6*DECH*KPD];
__device__ __nv_bfloat16 g_d2th[(size_t)6*MAXO*KPDEC], g_d2tl[(size_t)6*MAXO*KPDEC];

// ================= helpers =================
__device__ __forceinline__ uint32_t smem_u32(const void* p) {
    uint32_t a;
    asm("{ .reg .u64 t; cvta.to.shared.u64 t, %1; cvt.u32.u64 %0, t; }" : "=r"(a) : "l"(p));
    return a;
}
__device__ __forceinline__ void split_bf(float v, __nv_bfloat16& h, __nv_bfloat16& l) {
    h = __float2bfloat16(v);
    l = __float2bfloat16(v - __bfloat162float(h));
}
__device__ __forceinline__ uint32_t pk2(__nv_bfloat16 a, __nv_bfloat16 b) {
    return (uint32_t)__bfloat16_as_ushort(a) | ((uint32_t)__bfloat16_as_ushort(b) << 16);
}
__device__ __forceinline__ void split4(float4 v, uint2& hi, uint2& lo) {
    __nv_bfloat16 hx, hy, hz, hw, lx, ly, lz, lw;
    split_bf(v.x, hx, lx); split_bf(v.y, hy, ly);
    split_bf(v.z, hz, lz); split_bf(v.w, hw, lw);
    hi = make_uint2(pk2(hx, hy), pk2(hz, hw));
    lo = make_uint2(pk2(lx, ly), pk2(lz, lw));
}
#define LDSM_X4(r, a) \
    asm volatile("ldmatrix.sync.aligned.m8n8.x4.shared.b16 {%0,%1,%2,%3}, [%4];" \
        : "=r"((r)[0]), "=r"((r)[1]), "=r"((r)[2]), "=r"((r)[3]) : "r"(a))
__device__ __forceinline__ void mma_bf16(float* c, const uint32_t* a, const uint32_t* b) {
    asm volatile("mma.sync.aligned.m16n8k16.row.col.f32.bf16.bf16.f32 "
        "{%0,%1,%2,%3}, {%4,%5,%6,%7}, {%8,%9}, {%0,%1,%2,%3};"
        : "+f"(c[0]), "+f"(c[1]), "+f"(c[2]), "+f"(c[3])
        : "r"(a[0]), "r"(a[1]), "r"(a[2]), "r"(a[3]), "r"(b[0]), "r"(b[1]));
}
__device__ __forceinline__ void cpa16(uint32_t dst, const void* src, int bytes) {
    asm volatile("cp.async.cg.shared.global [%0], [%1], 16, %2;"
        :: "r"(dst), "l"(src), "r"(bytes) : "memory");
}
#define CPA_COMMIT() asm volatile("cp.async.commit_group;" ::: "memory")
#define CPA_WAIT0()  asm volatile("cp.async.wait_group 0;" ::: "memory")

// ================= HMMA GEMM (R12 proven) =================
#define TM 128
#define TN 128
#define TK 32
#define PITCH 40                 // bf16 elems per smem row (80B)
#define ARR_B 10240              // 128 rows x 80B
#define STAGE_B 40960
#define GEMM_SMEM (2 * STAGE_B)

#define GEMM_LOADER(T, BUF, AhP, AlP, BhP, BlP, LDA, LDB, R0, C0, MM, NCC) do { \
    int kt = (T) * TK; \
    uint32_t sst = sbase + (uint32_t)(BUF) * STAGE_B; \
    _Pragma("unroll") \
    for (int q = 0; q < 8; q++) { \
        int w = tid + (q & 1) * 256; \
        int r = w >> 2, k8 = w & 3; \
        int arr = q >> 1; \
        uint32_t dst = sst + (uint32_t)(arr * ARR_B + r * 80 + k8 * 16); \
        const __nv_bfloat16* base; int gr, ld, lim; \
        if (arr == 0)      { base = (AhP); gr = (R0) + r; ld = (LDA); lim = (MM); } \
        else if (arr == 1) { base = (AlP); gr = (R0) + r; ld = (LDA); lim = (MM); } \
        else if (arr == 2) { base = (BhP); gr = (C0) + r; ld = (LDB); lim = (NCC); } \
        else               { base = (BlP); gr = (C0) + r; ld = (LDB); lim = (NCC); } \
        int ok = (gr < lim) ? 16 : 0; \
        int grc = (gr < lim) ? gr : 0; \
        cpa16(dst, base + (size_t)grc * ld + kt + k8 * 8, ok); \
    } } while (0)

#define GEMM_MAINLOOP(AhP, AlP, BhP, BlP, LDA, LDB, R0, C0, MM, NCC, KPV) do { \
    int nt = (KPV) / TK; \
    GEMM_LOADER(0, 0, AhP, AlP, BhP, BlP, LDA, LDB, R0, C0, MM, NCC); CPA_COMMIT(); \
    int a_r = lane & 15; \
    int a_c = (lane >> 4) << 3; \
    int b_r = (lane & 7) + ((lane & 16) >> 1); \
    int b_c = ((lane >> 3) & 1) << 3; \
    for (int t = 0; t < nt; t++) { \
        CPA_WAIT0(); \
        __syncthreads(); \
        int buf = t & 1; \
        if (t + 1 < nt) { GEMM_LOADER(t + 1, buf ^ 1, AhP, AlP, BhP, BlP, LDA, LDB, R0, C0, MM, NCC); } \
        CPA_COMMIT(); \
        uint32_t sA = sbase + (uint32_t)buf * STAGE_B; \
        uint32_t sB = sA + 2 * ARR_B; \
        _Pragma("unroll") \
        for (int kk = 0; kk < TK; kk += 16) { \
            uint32_t ah[4][4], al[4][4], bh[2][4], bl[2][4]; \
            _Pragma("unroll") \
            for (int i = 0; i < 4; i++) { \
                uint32_t ad = sA + (uint32_t)((wm * 64 + i * 16 + a_r) * PITCH + kk + a_c) * 2; \
                LDSM_X4(ah[i], ad); \
                LDSM_X4(al[i], ad + ARR_B); \
            } \
            _Pragma("unroll") \
            for (int jj = 0; jj < 2; jj++) { \
                uint32_t bd = sB + (uint32_t)((wn * 32 + jj * 16 + b_r) * PITCH + kk + b_c) * 2; \
                LDSM_X4(bh[jj], bd); \
                LDSM_X4(bl[jj], bd + ARR_B); \
            } \
            _Pragma("unroll") \
            for (int i = 0; i < 4; i++) \
                _Pragma("unroll") \
                for (int jj = 0; jj < 2; jj++) \
                    _Pragma("unroll") \
                    for (int jx = 0; jx < 2; jx++) { \
                        int j = jj * 2 + jx; \
                        mma_bf16(acc[i][j], ah[i], &bh[jj][jx * 2]); \
                        mma_bf16(acc[i][j], ah[i], &bl[jj][jx * 2]); \
                        mma_bf16(acc[i][j], al[i], &bh[jj][jx * 2]); \
                    } \
        } \
    } } while (0)

__global__ void __launch_bounds__(256, 2) k_tgemm(
    const __nv_bfloat16* __restrict__ Ah, const __nv_bfloat16* __restrict__ Al, int lda,
    const __nv_bfloat16* __restrict__ Bh, const __nv_bfloat16* __restrict__ Bl, int ldb,
    const float* __restrict__ bias,
    float* __restrict__ C, int ldc,
    int M, int Nc, int Kp,
    float* __restrict__ stats, int do_stats)
{
    extern __shared__ char smem[];
    uint32_t sbase = smem_u32(smem);
    int tid = threadIdx.x, wid = tid >> 5, lane = tid & 31;
    int row0 = blockIdx.y * TM;
    int col0 = blockIdx.x * TN;
    int wm = wid & 1, wn = wid >> 1;

    float acc[4][4][4];
#pragma unroll
    for (int i = 0; i < 4; i++)
#pragma unroll
        for (int j = 0; j < 4; j++)
#pragma unroll
            for (int q = 0; q < 4; q++) acc[i][j][q] = 0.f;

    GEMM_MAINLOOP(Ah, Al, Bh, Bl, lda, ldb, row0, col0, M, Nc, Kp);

    int g = lane >> 2, t4 = lane & 3;
#pragma unroll
    for (int i = 0; i < 4; i++) {
        int r0c = row0 + wm * 64 + i * 16 + g;
        bool rv0 = (r0c < M), rv1 = (r0c + 8 < M);
#pragma unroll
        for (int j = 0; j < 4; j++) {
            int c0c = col0 + wn * 32 + j * 8 + t4 * 2;
            bool cv0 = (c0c < Nc), cv1 = (c0c + 1 < Nc);
            float b0 = cv0 ? bias[c0c] : 0.f;
            float b1 = cv1 ? bias[c0c + 1] : 0.f;
            float v0 = acc[i][j][0] + b0, v1 = acc[i][j][1] + b1;
            float v2 = acc[i][j][2] + b0, v3 = acc[i][j][3] + b1;
            if (rv0 && cv0) C[(size_t)r0c * ldc + c0c] = v0;
            if (rv0 && cv1) C[(size_t)r0c * ldc + c0c + 1] = v1;
            if (rv1 && cv0) C[(size_t)(r0c + 8) * ldc + c0c] = v2;
            if (rv1 && cv1) C[(size_t)(r0c + 8) * ldc + c0c + 1] = v3;
            acc[i][j][0] = (rv0 && cv0) ? v0 : 0.f;
            acc[i][j][1] = (rv0 && cv1) ? v1 : 0.f;
            acc[i][j][2] = (rv1 && cv0) ? v2 : 0.f;
            acc[i][j][3] = (rv1 && cv1) ? v3 : 0.f;
        }
    }
    if (do_stats) {
#pragma unroll
        for (int j = 0; j < 4; j++) {
            float se = 0.f, so = 0.f, qe = 0.f, qo = 0.f;
#pragma unroll
            for (int i = 0; i < 4; i++) {
                float v0 = acc[i][j][0], v1 = acc[i][j][1];
                float v2 = acc[i][j][2], v3 = acc[i][j][3];
                se += v0 + v2; so += v1 + v3;
                qe += v0 * v0 + v2 * v2; qo += v1 * v1 + v3 * v3;
            }
#pragma unroll
            for (int off = 4; off < 32; off <<= 1) {
                se += __shfl_xor_sync(0xffffffffu, se, off);
                so += __shfl_xor_sync(0xffffffffu, so, off);
                qe += __shfl_xor_sync(0xffffffffu, qe, off);
                qo += __shfl_xor_sync(0xffffffffu, qo, off);
            }
            if (lane < 4) {
                int ce = col0 + wn * 32 + j * 8 + lane * 2;
                if (ce < Nc)     { atomicAdd(&stats[ce], se);     atomicAdd(&stats[Nc + ce], qe); }
                if (ce + 1 < Nc) { atomicAdd(&stats[ce + 1], so); atomicAdd(&stats[Nc + ce + 1], qo); }
            }
        }
    }
}

// ======== batched decoder head-2 GEMM: blockIdx.z = head ========
__global__ void __launch_bounds__(256, 2) k_tgemm_dec2(
    const __nv_bfloat16* __restrict__ AhAll, const __nv_bfloat16* __restrict__ AlAll,
    const __nv_bfloat16* __restrict__ BhAll, const __nv_bfloat16* __restrict__ BlAll,
    const float* __restrict__ biasAll,
    float* __restrict__ outBase)
{
    const int DIMS[6] = {1024, 1111, 862, 1783, 966, 978};
    const int LDCS[6] = {1024, 1973, 1973, 2749, 2749, 978};
    const long BASE[6] = {
        2L * GG * DD,
        2L * GG * DD + (long)GG * 1024,
        2L * GG * DD + (long)GG * 1024 + 1111,
        2L * GG * DD + (long)GG * 1024 + (long)GG * 1973,
        2L * GG * DD + (long)GG * 1024 + (long)GG * 1973 + 1783,
        2L * GG * DD + (long)GG * 1024 + (long)GG * 1973 + (long)GG * 2749
    };
    int head = blockIdx.z;
    int Nc = DIMS[head];
    int ldc = LDCS[head];
    int col0 = blockIdx.x * TN;
    if (col0 >= Nc) return;
    int row0 = blockIdx.y * TM;
    const __nv_bfloat16* Ah = AhAll + (size_t)head * KPDEC;
    const __nv_bfloat16* Al = AlAll + (size_t)head * KPDEC;
    const __nv_bfloat16* Bh = BhAll + (size_t)head * MAXO * KPDEC;
    const __nv_bfloat16* Bl = BlAll + (size_t)head * MAXO * KPDEC;
    const float* bias = biasAll + (size_t)head * MAXO;
    float* C = outBase + BASE[head];
    const int lda = DEC_ALLP, ldb = KPDEC;
    const int M = GG;

    extern __shared__ char smem[];
    uint32_t sbase = smem_u32(smem);
    int tid = threadIdx.x, wid = tid >> 5, lane = tid & 31;
    int wm = wid & 1, wn = wid >> 1;

    float acc[4][4][4];
#pragma unroll
    for (int i = 0; i < 4; i++)
#pragma unroll
        for (int j = 0; j < 4; j++)
#pragma unroll
            for (int q = 0; q < 4; q++) acc[i][j][q] = 0.f;

    GEMM_MAINLOOP(Ah, Al, Bh, Bl, lda, ldb, row0, col0, M, Nc, KPDEC);

    int g = lane >> 2, t4 = lane & 3;
#pragma unroll
    for (int i = 0; i < 4; i++) {
        int r0c = row0 + wm * 64 + i * 16 + g;
#pragma unroll
        for (int j = 0; j < 4; j++) {
            int c0c = col0 + wn * 32 + j * 8 + t4 * 2;
            bool cv0 = (c0c < Nc), cv1 = (c0c + 1 < Nc);
            float b0 = cv0 ? bias[c0c] : 0.f;
            float b1 = cv1 ? bias[c0c + 1] : 0.f;
            if (cv0) C[(size_t)r0c * ldc + c0c] = acc[i][j][0] + b0;
            if (cv1) C[(size_t)r0c * ldc + c0c + 1] = acc[i][j][1] + b1;
            if (cv0) C[(size_t)(r0c + 8) * ldc + c0c] = acc[i][j][2] + b0;
            if (cv1) C[(size_t)(r0c + 8) * ldc + c0c + 1] = acc[i][j][3] + b1;
        }
    }
}

// ============ weight transpose + hi/lo convert (batched) ============
__global__ void k_wcvt(const float* __restrict__ in,
                       __nv_bfloat16* __restrict__ hi, __nv_bfloat16* __restrict__ lo,
                       int K, int N, int Kp) {
    __shared__ float t[32][33];
    int b = blockIdx.z;
    const float* I = in + (size_t)b * K * N;
    __nv_bfloat16* H = hi + (size_t)b * N * Kp;
    __nv_bfloat16* L = lo + (size_t)b * N * Kp;
    int r0 = blockIdx.y * 32, c0 = blockIdx.x * 32;
    int c = c0 + threadIdx.x;
#pragma unroll
    for (int i = 0; i < 32; i += 8) {
        int r = r0 + threadIdx.y + i;
        t[threadIdx.y + i][threadIdx.x] = (r < K && c < N) ? I[(size_t)r * N + c] : 0.f;
    }
    __syncthreads();
    int k = r0 + threadIdx.x;
#pragma unroll
    for (int i = 0; i < 32; i += 8) {
        int n = c0 + threadIdx.y + i;
        if (n < N && k < Kp) {
            float v = t[threadIdx.x][threadIdx.y + i];
            __nv_bfloat16 h, l; split_bf(v, h, l);
            H[(size_t)n * Kp + k] = h;
            L[(size_t)n * Kp + k] = l;
        }
    }
}

// vectorized fp32 -> padded bf16 hi/lo; also zeroes stats[0..zcount)
__global__ void k_cvtpad4(const float* __restrict__ in,
                          uint2* __restrict__ hi, uint2* __restrict__ lo,
                          long total4, int C, int Cp,
                          float* __restrict__ stats, int zcount) {
    long i = (long)blockIdx.x * blockDim.x + threadIdx.x;
    if (i >= total4) return;
    if (stats && i < zcount) stats[i] = 0.f;
    int w4 = Cp >> 2;
    int n = (int)(i / w4);
    int c = ((int)(i - (long)n * w4)) << 2;
    float4 v = make_float4(0.f, 0.f, 0.f, 0.f);
    if (c < C) v = *(const float4*)(in + (size_t)n * C + c);
    uint2 h, l; split4(v, h, l);
    hi[i] = h; lo[i] = l;
}

// BN apply + act + hi/lo convert, head-batched; also zeroes stats[0..zcount)
__global__ void k_bnact_cvt4(const float* __restrict__ X,
                             const float* __restrict__ scale, const float* __restrict__ shift,
                             uint2* __restrict__ hi, uint2* __restrict__ lo,
                             long total4, int C, int Cp, int nheads, int gelu,
                             float* __restrict__ stats, int zcount) {
    long i = (long)blockIdx.x * blockDim.x + threadIdx.x;
    if (i >= total4) return;
    if (stats && i < zcount) stats[i] = 0.f;
    int w4 = (nheads * Cp) >> 2;
    int n = (int)(i / w4);
    int col = ((int)(i - (long)n * w4)) << 2;
    int head = col / Cp;
    int c = col - head * Cp;
    float4 r4 = make_float4(0.f, 0.f, 0.f, 0.f);
    if (c < C) {
        int sidx = head * C + c;
        const float4 x = *(const float4*)(X + (size_t)n * (nheads * C) + sidx);
        const float4 sc = *(const float4*)(scale + sidx);
        const float4 sh = *(const float4*)(shift + sidx);
        float v0 = x.x * sc.x + sh.x, v1 = x.y * sc.y + sh.y;
        float v2 = x.z * sc.z + sh.z, v3 = x.w * sc.w + sh.w;
        if (gelu) {
            const float k = 0.70710678118654752f;
            r4 = make_float4(0.5f * v0 * (1.f + erff(v0 * k)), 0.5f * v1 * (1.f + erff(v1 * k)),
                             0.5f * v2 * (1.f + erff(v2 * k)), 0.5f * v3 * (1.f + erff(v3 * k)));
        } else {
            r4 = make_float4(fmaxf(v0, 0.f), fmaxf(v1, 0.f), fmaxf(v2, 0.f), fmaxf(v3, 0.f));
        }
    }
    uint2 h, l; split4(r4, h, l);
    hi[i] = h; lo[i] = l;
}

// ================= elementwise =================
__global__ void k_zero_u(unsigned* p, int n) {
    int i = blockIdx.x * blockDim.x + threadIdx.x;
    if (i < n) p[i] = 0u;
}
// h = atom_emb[x_idx]; z = (1+eps0)*h
__global__ void k_init_h4(const float4* __restrict__ atom_emb, const int* __restrict__ x_idx,
                          const float* __restrict__ eps0,
                          float4* __restrict__ h, float4* __restrict__ z) {
    long i = (long)blockIdx.x * blockDim.x + threadIdx.x;
    const int C4 = DD / 4;
    long total = (long)NN * C4;
    if (i >= total) return;
    int n = (int)(i / C4);
    int d = (int)(i - (long)n * C4);
    float4 v = atom_emb[(size_t)x_idx[n] * C4 + d];
    h[i] = v;
    float e = 1.f + *eps0;
    z[i] = make_float4(e * v.x, e * v.y, e * v.z, e * v.w);
}
// edge: msg = relu(h[src]+e); vector RED into z[dst]
__global__ void k_edge4(const float4* __restrict__ h, const float4* __restrict__ ee,
                        const int* __restrict__ attr, const int* __restrict__ ei,
                        float* __restrict__ z) {
    long i = (long)blockIdx.x * blockDim.x + threadIdx.x;
    const int C4 = DD / 4;
    long total = (long)EE * C4;
    if (i >= total) return;
    int e = (int)(i / C4);
    int q = (int)(i - (long)e * C4);
    int src = ei[e];
    int dst = ei[EE + e];
    float4 a = h[(size_t)src * C4 + q];
    float4 b = ee[(size_t)attr[e] * C4 + q];
    float m0 = fmaxf(a.x + b.x, 0.f);
    float m1 = fmaxf(a.y + b.y, 0.f);
    float m2 = fmaxf(a.z + b.z, 0.f);
    float m3 = fmaxf(a.w + b.w, 0.f);
    float* zp = z + (size_t)dst * DD + q * 4;
    asm volatile("red.global.add.v4.f32 [%0], {%1,%2,%3,%4};"
        :: "l"(zp), "f"(m0), "f"(m1), "f"(m2), "f"(m3) : "memory");
}
__global__ void k_bn_final(const float* __restrict__ sums, float invM, int C,
                           const float* __restrict__ gamma, const float* __restrict__ beta,
                           float* __restrict__ scale, float* __restrict__ shift) {
    int c = blockIdx.x * blockDim.x + threadIdx.x;
    if (c >= C) return;
    float mean = sums[c] * invM;
    float var  = sums[C + c] * invM - mean * mean;
    float istd = rsqrtf(var + 1e-5f);
    float sc = istd * gamma[c];
    scale[c] = sc;
    shift[c] = beta[c] - mean * sc;
}
__device__ __forceinline__ unsigned enc_f(float x) {
    unsigned u = __float_as_uint(x);
    return (u & 0x80000000u) ? ~u : (u | 0x80000000u);
}
// mode 1: h += relu(bn(X)); mode 2: h += bn(X).
// If znext: znext = (1+eps)*h_new. If hg: segment-max h_new into hg (needs batch).
__global__ void k_bn_apply4(float4* __restrict__ X, float4* __restrict__ res,
                            const float4* __restrict__ scale, const float4* __restrict__ shift,
                            long total4, int C4, int mode,
                            const float* __restrict__ epsn, float4* __restrict__ znext,
                            const int* __restrict__ batch, unsigned* __restrict__ hg) {
    long i = (long)blockIdx.x * blockDim.x + threadIdx.x;
    if (i >= total4) return;
    int c = (int)(i % C4);
    float4 x = X[i], sc = scale[c], sh = shift[c];
    float v0 = x.x * sc.x + sh.x, v1 = x.y * sc.y + sh.y;
    float v2 = x.z * sc.z + sh.z, v3 = x.w * sc.w + sh.w;
    float4 r = res[i];
    float4 o;
    if (mode == 1) {
        o = make_float4(r.x + fmaxf(v0, 0.f), r.y + fmaxf(v1, 0.f),
                        r.z + fmaxf(v2, 0.f), r.w + fmaxf(v3, 0.f));
    } else {
        o = make_float4(r.x + v0, r.y + v1, r.z + v2, r.w + v3);
    }
    res[i] = o;
    if (znext) {
        float e = 1.f + *epsn;
        znext[i] = make_float4(e * o.x, e * o.y, e * o.z, e * o.w);
    }
    if (hg) {
        int n = (int)(i / C4);
        unsigned* hp = hg + (size_t)batch[n] * DD + (size_t)c * 4;
        atomicMax(hp + 0, enc_f(o.x));
        atomicMax(hp + 1, enc_f(o.y));
        atomicMax(hp + 2, enc_f(o.z));
        atomicMax(hp + 3, enc_f(o.w));
    }
}
__global__ void k_silu_cvt4(const unsigned* __restrict__ hg,
                            uint2* __restrict__ hi, uint2* __restrict__ lo,
                            long total4, int C, int Cp) {
    long i = (long)blockIdx.x * blockDim.x + threadIdx.x;
    if (i >= total4) return;
    int w4 = Cp >> 2;
    int n = (int)(i / w4);
    int c = ((int)(i - (long)n * w4)) << 2;
    float4 r4 = make_float4(0.f, 0.f, 0.f, 0.f);
    if (c < C) {
        uint4 u4 = *(const uint4*)(hg + (size_t)n * C + c);
        float* rp = &r4.x;
        unsigned uu[4] = {u4.x, u4.y, u4.z, u4.w};
#pragma unroll
        for (int q = 0; q < 4; q++) {
            unsigned u = uu[q];
            u = (u & 0x80000000u) ? (u & 0x7fffffffu) : ~u;
            float x = __uint_as_float(u);
            rp[q] = x / (1.f + expf(-x));
        }
    }
    uint2 h, l; split4(r4, h, l);
    hi[i] = h; lo[i] = l;
}
__global__ void k_split(const float* __restrict__ d, float* __restrict__ out, long offS) {
    long i = (long)blockIdx.x * blockDim.x + threadIdx.x;
    long total = (long)GG * HH;
    if (i >= total) return;
    int g = (int)(i / HH);
    int c = (int)(i - (long)g * HH);
    float v = d[i];
    if (c < DD) {
        out[(size_t)g * DD + c] = v;
    } else {
        float sp = fmaxf(v, 0.f) + log1pf(expf(-fabsf(v))) + 1e-7f;
        out[offS + (size_t)g * DD + (c - DD)] = sp;
    }
}

// ================= host side =================
static void tgemm(const __nv_bfloat16* Ah, const __nv_bfloat16* Al, int lda,
                  const __nv_bfloat16* Bh, const __nv_bfloat16* Bl, int ldb,
                  const float* bias, float* C, int ldc,
                  int M, int Nc, int Kp, float* stats, int do_stats) {
    dim3 gr((Nc + TN - 1) / TN, (M + TM - 1) / TM);
    k_tgemm<<<gr, 256, GEMM_SMEM>>>(Ah, Al, lda, Bh, Bl, ldb, bias, C, ldc, M, Nc, Kp, stats, do_stats);
}
static void wcvt(const float* in, __nv_bfloat16* hi, __nv_bfloat16* lo,
                 int K, int N, int Kp, int B) {
    dim3 bl(32, 8), gr((N + 31) / 32, (Kp + 31) / 32, B);
    k_wcvt<<<gr, bl>>>(in, hi, lo, K, N, Kp);
}

extern "C" void kernel_launch(void* const* d_in, const int* in_sizes, int n_in,
                              void* d_out, int out_size) {
    const float* atom_emb   = (const float*)d_in[0];
    const float* edge_emb   = (const float*)d_in[1];
    const float* eps        = (const float*)d_in[2];
    const float* conv_w1    = (const float*)d_in[3];
    const float* conv_b1    = (const float*)d_in[4];
    const float* conv_bn1_g = (const float*)d_in[5];
    const float* conv_bn1_b = (const float*)d_in[6];
    const float* conv_w2    = (const float*)d_in[7];
    const float* conv_b2    = (const float*)d_in[8];
    const float* bn_g       = (const float*)d_in[9];
    const float* bn_b       = (const float*)d_in[10];
    const float* dist_w     = (const float*)d_in[11];
    const float* dist_b     = (const float*)d_in[12];
    const float* dec_w1     = (const float*)d_in[13];
    const float* dec_b1     = (const float*)d_in[14];
    const float* dec_bn_g   = (const float*)d_in[15];
    const float* dec_bn_b   = (const float*)d_in[16];
    const float* dec_w2     = (const float*)d_in[17];
    const float* dec_b2     = (const float*)d_in[18];
    const int*   x_idx      = (const int*)d_in[19];
    const int*   edge_attr  = (const int*)d_in[20];
    const int*   edge_index = (const int*)d_in[21];
    const int*   batch      = (const int*)d_in[22];
    float* out = (float*)d_out;

    cudaFuncSetAttribute(k_tgemm, cudaFuncAttributeMaxDynamicSharedMemorySize, GEMM_SMEM);
    cudaFuncSetAttribute(k_tgemm_dec2, cudaFuncAttributeMaxDynamicSharedMemorySize, GEMM_SMEM);

    float *h, *z, *y, *stats, *scale, *shift, *dbuf, *dz;
    unsigned* hg;
    __nv_bfloat16 *zh, *zl, *yh, *yl, *sh, *sl, *muh, *mul, *dzh, *dzl;
    __nv_bfloat16 *w1th, *w1tl, *w2th, *w2tl, *dwth, *dwtl, *d1th, *d1tl, *d2th, *d2tl;
    cudaGetSymbolAddress((void**)&h,     g_h);
    cudaGetSymbolAddress((void**)&z,     g_z);
    cudaGetSymbolAddress((void**)&y,     g_y);
    cudaGetSymbolAddress((void**)&stats, g_stats);
    cudaGetSymbolAddress((void**)&scale, g_scale);
    cudaGetSymbolAddress((void**)&shift, g_shift);
    cudaGetSymbolAddress((void**)&hg,    g_hg);
    cudaGetSymbolAddress((void**)&dbuf,  g_d);
    cudaGetSymbolAddress((void**)&dz,    g_dz);
    cudaGetSymbolAddress((void**)&zh,    g_zh);   cudaGetSymbolAddress((void**)&zl,  g_zl);
    cudaGetSymbolAddress((void**)&yh,    g_yh);   cudaGetSymbolAddress((void**)&yl,  g_yl);
    cudaGetSymbolAddress((void**)&sh,    g_sh);   cudaGetSymbolAddress((void**)&sl,  g_sl);
    cudaGetSymbolAddress((void**)&muh,   g_muh);  cudaGetSymbolAddress((void**)&mul, g_mul);
    cudaGetSymbolAddress((void**)&dzh,   g_dzh);  cudaGetSymbolAddress((void**)&dzl, g_dzl);
    cudaGetSymbolAddress((void**)&w1th,  g_w1th); cudaGetSymbolAddress((void**)&w1tl, g_w1tl);
    cudaGetSymbolAddress((void**)&w2th,  g_w2th); cudaGetSymbolAddress((void**)&w2tl, g_w2tl);
    cudaGetSymbolAddress((void**)&dwth,  g_dwth); cudaGetSymbolAddress((void**)&dwtl, g_dwtl);
    cudaGetSymbolAddress((void**)&d1th,  g_d1th); cudaGetSymbolAddress((void**)&d1tl, g_d1tl);
    cudaGetSymbolAddress((void**)&d2th,  g_d2th); cudaGetSymbolAddress((void**)&d2tl, g_d2tl);

    // transpose + convert weights once per call
    wcvt(conv_w1, w1th, w1tl, DD, HH, KPD, LL);
    wcvt(conv_w2, w2th, w2tl, HH, DD, KPH, LL);
    wcvt(dist_w,  dwth, dwtl, DD, HH, KPD, 1);
    wcvt(dec_w1,  d1th, d1tl, DD, DECH, KPD, 6);
    wcvt(dec_w2,  d2th, d2tl, DECH, MAXO, KPDEC, 6);

    const long ND  = (long)NN * DD;
    const long ND4 = ND / 4;
    const long ED4 = (long)EE * DD / 4;
    const long NZP4 = (long)NN * KPD / 4;
    const long NYP4 = (long)NN * KPH / 4;
    int GD = GG * DD;

    k_init_h4<<<(int)((ND4 + 255) / 256), 256>>>((const float4*)atom_emb, x_idx, eps,
                                                 (float4*)h, (float4*)z);

    for (int l = 0; l < LL; l++) {
        k_edge4<<<(int)((ED4 + 255) / 256), 256>>>((const float4*)h,
                 (const float4*)(edge_emb + (size_t)l * 5 * DD), edge_attr, edge_index, z);
        k_cvtpad4<<<(int)((NZP4 + 255) / 256), 256>>>(z, (uint2*)zh, (uint2*)zl, NZP4, DD, KPD,
                                                      stats, 2 * HH);
        tgemm(zh, zl, KPD, w1th + (size_t)l * HH * KPD, w1tl + (size_t)l * HH * KPD, KPD,
              conv_b1 + (size_t)l * HH, y, HH, NN, HH, KPD, stats, 1);
        k_bn_final<<<(HH + 255) / 256, 256>>>(stats, 1.f / (float)NN, HH,
              conv_bn1_g + (size_t)l * HH, conv_bn1_b + (size_t)l * HH, scale, shift);
        k_bnact_cvt4<<<(int)((NYP4 + 255) / 256), 256>>>(y, scale, shift,
              (uint2*)yh, (uint2*)yl, NYP4, HH, KPH, 1, 0, stats, 2 * DD);
        tgemm(yh, yl, KPH, w2th + (size_t)l * DD * KPH, w2tl + (size_t)l * DD * KPH, KPH,
              conv_b2 + (size_t)l * DD, z, DD, NN, DD, KPH, stats, 1);
        k_bn_final<<<(DD + 255) / 256, 256>>>(stats, 1.f / (float)NN, DD,
              bn_g + (size_t)l * DD, bn_b + (size_t)l * DD, scale, shift);
        bool more = (l < LL - 1);
        if (!more) {
            // zero hg before fused segmax in the final bn_apply
            k_zero_u<<<(GD + 255) / 256, 256>>>(hg, GD);
        }
        k_bn_apply4<<<(int)((ND4 + 255) / 256), 256>>>((float4*)z, (float4*)h,
              (const float4*)scale, (const float4*)shift, ND4, DD / 4, more ? 1 : 2,
              more ? (eps + l + 1) : nullptr, more ? (float4*)z : nullptr,
              more ? nullptr : batch, more ? nullptr : hg);
    }

    // pooled max -> silu -> bf16
    const long GSP4 = (long)GG * KPD / 4;
    k_silu_cvt4<<<(int)((GSP4 + 255) / 256), 256>>>(hg, (uint2*)sh, (uint2*)sl, GSP4, DD, KPD);

    // d = silu(h_graph) @ dist_w + dist_b
    tgemm(sh, sl, KPD, dwth, dwtl, KPD, dist_b, dbuf, HH, GG, HH, KPD, stats, 0);

    const long OFF_SG = (long)GG * DD;
    k_split<<<(int)(((long)GG * HH + 255) / 256), 256>>>(dbuf, out, OFF_SG);
    k_cvtpad4<<<(int)((GSP4 + 255) / 256), 256>>>(out, (uint2*)muh, (uint2*)mul, GSP4, DD, KPD,
                                                  stats, 2 * DEC_ALL);

    // ===== batched decoder heads =====
    tgemm(muh, mul, KPD, d1th, d1tl, KPD, dec_b1, dz, DEC_ALL, GG, DEC_ALL, KPD, stats, 1);
    k_bn_final<<<(DEC_ALL + 255) / 256, 256>>>(stats, 1.f / (float)GG, DEC_ALL,
          dec_bn_g, dec_bn_b, scale, shift);
    const long GDP4 = (long)GG * DEC_ALLP / 4;
    k_bnact_cvt4<<<(int)((GDP4 + 255) / 256), 256>>>(dz, scale, shift,
          (uint2*)dzh, (uint2*)dzl, GDP4, DECH, KPDEC, 6, 1, nullptr, 0);
    {
        dim3 gr((MAXO + TN - 1) / TN, (GG + TM - 1) / TM, 6);
        k_tgemm_dec2<<<gr, 256, GEMM_SMEM>>>(dzh, dzl, d2th, d2tl, dec_b2, out);
    }
}